// round 2
// baseline (speedup 1.0000x reference)
#include <cuda_runtime.h>
#include <math.h>

#define BQ   16
#define TT   1000
#define MEL  80
#define HID  512
#define NCLS 64
#define NROW (BQ*TT)

#define SER_NCTA    128
#define SER_NC      4          // HID / SER_NCTA
#define SER_THREADS 256

// ---------------- scratch (static device globals; no allocations) ----------------
__device__ float g_be0[NROW*HID];     // base_eff of layer0 == input to layer1
__device__ float g_be1[NROW*HID];     // base_eff of layer1 (second half of ys)
__device__ float g_h1 [NROW*HID];     // h1 trace (first half of ys)
__device__ float g_xs1[NROW];         // per-(b,t) x_scale for layer1
__device__ float g_h  [BQ*HID];       // current h1
__device__ float g_err[BQ*HID];       // current error vector
__device__ float g_norm2[2][BQ];      // rotating squared-norm accumulators
__device__ unsigned g_bcount;         // grid barrier counter (monotonic per launch)

__device__ __forceinline__ float sigm(float x){ return 1.0f/(1.0f+expf(-x)); }

// ---------------- init: reset cross-launch state ----------------
__global__ void k_init(){
  int i = threadIdx.x;
  if (i==0) g_bcount = 0u;
  if (i<2*BQ) (&g_norm2[0][0])[i] = 0.f;
  for (int j=i; j<BQ*HID; j+=blockDim.x) g_h[j]=0.f;
}

// ---------------- be0 = clip(feats/||feats||) @ B0^T ; xs1 = ||be0|| ----------------
__global__ __launch_bounds__(256) void k_be0(const float* __restrict__ feats,
                                             const float* __restrict__ B0){
  __shared__ float xn[16][MEL];
  __shared__ float snorm[16];
  __shared__ float sxs[16];
  int tid = threadIdx.x;
  int row0 = blockIdx.x*16;
  for (int i=tid;i<16*MEL;i+=256)
    xn[i/MEL][i%MEL] = feats[row0*MEL + i];
  __syncthreads();
  if (tid<16){
    float s=0.f;
    #pragma unroll
    for (int k=0;k<MEL;k++){ float v=xn[tid][k]; s+=v*v; }
    sxs[tid]=fmaxf(sqrtf(s),1e-6f);
    snorm[tid]=0.f;
  }
  __syncthreads();
  for (int i=tid;i<16*MEL;i+=256){
    int r=i/MEL;
    float v = xn[r][i%MEL]/sxs[r];
    xn[r][i%MEL] = fminf(fmaxf(v,-1.f),1.f);
  }
  __syncthreads();
  int n0=tid, n1=tid+256;
  float a0[16], a1_[16];
  #pragma unroll
  for (int r=0;r<16;r++){ a0[r]=0.f; a1_[r]=0.f; }
  for (int k=0;k<MEL;k+=4){
    float4 w0 = *(const float4*)&B0[n0*MEL+k];
    float4 w1 = *(const float4*)&B0[n1*MEL+k];
    #pragma unroll
    for (int r=0;r<16;r++){
      float4 x = *(const float4*)&xn[r][k];
      a0 [r] += w0.x*x.x + w0.y*x.y + w0.z*x.z + w0.w*x.w;
      a1_[r] += w1.x*x.x + w1.y*x.y + w1.z*x.z + w1.w*x.w;
    }
  }
  #pragma unroll
  for (int r=0;r<16;r++){
    g_be0[(row0+r)*HID+n0]=a0[r];
    g_be0[(row0+r)*HID+n1]=a1_[r];
    atomicAdd(&snorm[r], a0[r]*a0[r] + a1_[r]*a1_[r]);
  }
  __syncthreads();
  if (tid<16) g_xs1[row0+tid] = fmaxf(sqrtf(snorm[tid]),1e-6f);
}

// ---------------- be1 = clip(be0/xs1) @ B1^T ----------------
__global__ __launch_bounds__(256) void k_be1(const float* __restrict__ B1){
  __shared__ float xn[16][HID];
  __shared__ float sxs[16];
  int tid=threadIdx.x;
  int row0=blockIdx.x*16;
  if (tid<16) sxs[tid]=g_xs1[row0+tid];
  __syncthreads();
  for (int i=tid;i<16*HID;i+=256){
    int r=i>>9;
    float v = g_be0[row0*HID + i]/sxs[r];
    xn[r][i&511] = fminf(fmaxf(v,-1.f),1.f);
  }
  __syncthreads();
  int n0=tid, n1=tid+256;
  float a0[16], a1_[16];
  #pragma unroll
  for (int r=0;r<16;r++){ a0[r]=0.f; a1_[r]=0.f; }
  for (int k=0;k<HID;k+=4){
    float4 w0 = *(const float4*)&B1[n0*HID+k];
    float4 w1 = *(const float4*)&B1[n1*HID+k];
    #pragma unroll
    for (int r=0;r<16;r++){
      float4 x = *(const float4*)&xn[r][k];
      a0 [r] += w0.x*x.x + w0.y*x.y + w0.z*x.z + w0.w*x.w;
      a1_[r] += w1.x*x.x + w1.y*x.y + w1.z*x.z + w1.w*x.w;
    }
  }
  #pragma unroll
  for (int r=0;r<16;r++){
    g_be1[(row0+r)*HID+n0]=a0[r];
    g_be1[(row0+r)*HID+n1]=a1_[r];
  }
}

// ---------------- grid barrier (monotonic; counter reset by k_init) ----------------
__device__ __forceinline__ void gridbar(unsigned &target){
  __threadfence();
  __syncthreads();
  if (threadIdx.x==0){
    target += SER_NCTA;
    atomicAdd(&g_bcount, 1u);
    while (*((volatile unsigned*)&g_bcount) < target) { }
  }
  __syncthreads();
}

// ---------------- serial layer-1 recurrence ----------------
__global__ __launch_bounds__(SER_THREADS) void k_serial(
    const float* __restrict__ C1, const float* __restrict__ W1,
    const float* __restrict__ a1, const float* __restrict__ tau,
    const float* __restrict__ gam){
  __shared__ float xbuf[BQ*HID];   // staged h (phase1) / err (phase2)
  __shared__ float h_own[64];      // old h for this CTA's (b,n) slice
  __shared__ float siga[SER_NC];
  __shared__ float snorm[BQ];
  int tid=threadIdx.x, cta=blockIdx.x;
  int nbase=cta*SER_NC;
  if (tid<SER_NC) siga[tid]=sigm(a1[nbase+tid]);
  if (tid<BQ)     snorm[tid]=0.f;
  float tauv=tau[0], gamv=gam[0];
  int grp=tid>>2, l4=tid&3;
  int b=grp>>2, nl=grp&3;
  int nglob=nbase+nl;
  const float4* wc4 = (const float4*)&C1[nglob*HID];  // L1-resident across steps
  const float4* ww4 = (const float4*)&W1[nglob*HID];
  unsigned target=0;
  __syncthreads();

  for (int t=0;t<TT;t++){
    // ---- phase 1: p = tanh(h@C1^T)*xs ; err = be0 - p ; partial norms ----
    for (int i=tid;i<BQ*HID/4;i+=SER_THREADS)
      ((float4*)xbuf)[i] = __ldcg(((const float4*)g_h)+i);
    __syncthreads();
    if (l4==0) h_own[grp] = xbuf[b*HID+nglob];
    float xs = __ldg(&g_xs1[b*TT+t]);
    float acc=0.f;
    #pragma unroll
    for (int j=0;j<32;j++){
      float4 w = __ldg(&wc4[l4 + j*4]);
      float4 x = *(const float4*)&xbuf[b*HID + l4*4 + j*16];
      acc += w.x*x.x + w.y*x.y + w.z*x.z + w.w*x.w;
    }
    acc += __shfl_down_sync(0xffffffffu,acc,2);
    acc += __shfl_down_sync(0xffffffffu,acc,1);
    if (l4==0){
      float p = tanhf(acc)*xs;
      float e = __ldg(&g_be0[(b*TT+t)*HID+nglob]) - p;
      __stcg(&g_err[b*HID+nglob], e);
      atomicAdd(&snorm[b], e*e);
    }
    __syncthreads();
    if (tid<BQ){ atomicAdd(&g_norm2[t&1][tid], snorm[tid]); snorm[tid]=0.f; }
    gridbar(target);

    // ---- phase 2: surprise ; ee = err@W1^T ; h update ----
    if (cta==0 && tid<BQ) __stcg(&g_norm2[(t+1)&1][tid], 0.f);
    for (int i=tid;i<BQ*HID/4;i+=SER_THREADS)
      ((float4*)xbuf)[i] = __ldcg(((const float4*)g_err)+i);
    __syncthreads();
    float n2 = __ldcg(&g_norm2[t&1][b]);
    float rel = fminf(sqrtf(n2)/xs, 4.0f);
    float s = sigm((rel - tauv)/gamv);
    float acc2=0.f;
    #pragma unroll
    for (int j=0;j<32;j++){
      float4 w = __ldg(&ww4[l4 + j*4]);
      float4 x = *(const float4*)&xbuf[b*HID + l4*4 + j*16];
      acc2 += w.x*x.x + w.y*x.y + w.z*x.z + w.w*x.w;
    }
    acc2 += __shfl_down_sync(0xffffffffu,acc2,2);
    acc2 += __shfl_down_sync(0xffffffffu,acc2,1);
    if (l4==0){
      float hol = h_own[grp];
      float be1v = __ldg(&g_be1[(b*TT+t)*HID+nglob]);
      float ih = 0.2f*hol + 0.6f*be1v + 0.2f*s*acc2;
      float g = s*siga[nl];
      float hn = hol*(1.f-g) + tanhf(ih)*g;
      __stcg(&g_h[b*HID+nglob], hn);
      g_h1[(b*TT+t)*HID+nglob] = hn;
    }
    gridbar(target);
  }
}

// ---------------- head: out = [h1, be1] @ head_w^T + head_b ----------------
__global__ __launch_bounds__(256) void k_head(const float* __restrict__ hw,
                                              const float* __restrict__ hb,
                                              float* __restrict__ out){
  __shared__ float sh[8*1024];
  __shared__ float sred[4*8*64];
  int tid=threadIdx.x;
  int row0=blockIdx.x*8;
  for (int i=tid;i<8*1024;i+=256){
    int r=i>>10, j=i&1023;
    sh[i] = (j<512)? g_h1[(row0+r)*HID+j] : g_be1[(row0+r)*HID+(j-512)];
  }
  __syncthreads();
  int c=tid&63, q=tid>>6;
  float acc[8];
  #pragma unroll
  for (int r=0;r<8;r++) acc[r]=0.f;
  for (int k=q*256;k<q*256+256;k+=4){
    float4 w = *(const float4*)&hw[c*1024+k];
    #pragma unroll
    for (int r=0;r<8;r++){
      float4 x = *(const float4*)&sh[r*1024+k];
      acc[r] += w.x*x.x + w.y*x.y + w.z*x.z + w.w*x.w;
    }
  }
  #pragma unroll
  for (int r=0;r<8;r++) sred[(q*8+r)*64+c]=acc[r];
  __syncthreads();
  for (int i=tid;i<8*64;i+=256){
    int r=i>>6, cc=i&63;
    out[(row0+r)*NCLS+cc] = sred[r*64+cc] + sred[(8+r)*64+cc]
                          + sred[(16+r)*64+cc] + sred[(24+r)*64+cc] + __ldg(&hb[cc]);
  }
}

// ---------------- launch ----------------
extern "C" void kernel_launch(void* const* d_in, const int* in_sizes, int n_in,
                              void* d_out, int out_size){
  const float* feats=(const float*)d_in[0];
  const float* B0  =(const float*)d_in[2];
  const float* C1  =(const float*)d_in[7];
  const float* B1  =(const float*)d_in[8];
  const float* W1  =(const float*)d_in[9];
  const float* a1  =(const float*)d_in[10];
  const float* tau1=(const float*)d_in[11];
  const float* gam1=(const float*)d_in[12];
  const float* hw  =(const float*)d_in[13];
  const float* hb  =(const float*)d_in[14];
  float* out=(float*)d_out;

  k_init  <<<1,256>>>();
  k_be0   <<<NROW/16,256>>>(feats,B0);
  k_be1   <<<NROW/16,256>>>(B1);
  k_serial<<<SER_NCTA,SER_THREADS>>>(C1,W1,a1,tau1,gam1);
  k_head  <<<NROW/8,256>>>(hw,hb,out);
}